// round 1
// baseline (speedup 1.0000x reference)
#include <cuda_runtime.h>
#include <cstdint>
#include <cstddef>

#define NVEC 1024
#define NDIM 64
#define NHID 32
#define NW   10
#define NB   16
#define NOFF 11

// Scratch (no allocations allowed): device globals.
__device__ float g_w[NW * NB * NOFF * NVEC];   // per-layer sparse W values [i][b][o][n]
__device__ float g_V[NB * NVEC * NDIM];        // final V
__device__ float g_part[NB * 8 * 10];          // partial sums for output GEMM

// ---------- f32x2 packed helpers (sm_103a FFMA2) ----------
__device__ __forceinline__ unsigned long long pack2(float x, float y) {
    unsigned long long r;
    asm("mov.b64 %0, {%1, %2};" : "=l"(r) : "f"(x), "f"(y));
    return r;
}
__device__ __forceinline__ void fma2(unsigned long long& d, unsigned long long a, unsigned long long b) {
    asm("fma.rn.f32x2 %0, %1, %2, %0;" : "+l"(d) : "l"(a), "l"(b));
}
__device__ __forceinline__ float2 unpack2(unsigned long long v) {
    float lo, hi;
    asm("mov.b64 {%0, %1}, %2;" : "=f"(lo), "=f"(hi) : "l"(v));
    return make_float2(lo, hi);
}
__device__ __forceinline__ float gelu_exact(float x) {
    return 0.5f * x * (1.0f + erff(x * 0.70710678f));
}

// ---------------------------------------------------------------------------
// Kernel 1: precompute sparse W values for ALL layers in parallel.
// grid (4 n-tiles, 16 b, 10 layers), 256 threads; thread t owns n = n0 + t.
// smem: fW2 tile transposed [col][h] (stride 34 -> conflict-free LDS.64 pairs),
//       fW1 [d][h], fb1.
// ---------------------------------------------------------------------------
#define SW2_COLS   768          // columns needed: [n0, n0+255+512]
#define SW2_STRIDE 34           // even (8B-aligned pairs) + conflict-free
#define PRE_SMEM   ((SW2_COLS * SW2_STRIDE + NDIM * NHID + NHID) * 4)

__global__ void __launch_bounds__(256) precompute_kernel(
    const float* __restrict__ data, const float* __restrict__ fW1,
    const float* __restrict__ fb1,  const float* __restrict__ fW2,
    const float* __restrict__ fb2)
{
    extern __shared__ float sm[];
    float* sw2t = sm;                               // [768][34]
    float* sw1  = sm + SW2_COLS * SW2_STRIDE;       // [64][32]
    float* sfb1 = sw1 + NDIM * NHID;                // [32]

    const int t  = threadIdx.x;
    const int n0 = blockIdx.x * 256;
    const int b  = blockIdx.y;
    const int i  = blockIdx.z;

    // Stage fW1 / fb1 (coalesced).
    for (int idx = t; idx < NDIM * NHID; idx += 256)
        sw1[idx] = fW1[i * NDIM * NHID + idx];
    if (t < NHID) sfb1[t] = fb1[i * NHID + t];

    // Stage fW2 columns [n0 .. n0+767] mod 1024, transposed to [col][h].
    for (int idx = t; idx < NHID * SW2_COLS; idx += 256) {
        int hh  = idx / SW2_COLS;
        int c   = idx - hh * SW2_COLS;
        int col = (n0 + c) & (NVEC - 1);
        sw2t[c * SW2_STRIDE + hh] = fW2[(size_t)(i * NHID + hh) * NVEC + col];
    }
    __syncthreads();

    const int n = n0 + t;

    // h = gelu(data_row @ fW1 + fb1), accumulated as 16 packed f32x2 pairs.
    unsigned long long acc2[16];
#pragma unroll
    for (int k = 0; k < 16; k++)
        acc2[k] = *reinterpret_cast<const unsigned long long*>(&sfb1[2 * k]);

    const float4* rowv =
        reinterpret_cast<const float4*>(data + ((size_t)(b * NVEC) + n) * NDIM);
#pragma unroll 4
    for (int dq = 0; dq < 16; dq++) {
        float4 X = __ldg(rowv + dq);
#pragma unroll
        for (int dd = 0; dd < 4; dd++) {
            float xd = (dd == 0) ? X.x : (dd == 1) ? X.y : (dd == 2) ? X.z : X.w;
            unsigned long long xx = pack2(xd, xd);
            const unsigned long long* w1p =
                reinterpret_cast<const unsigned long long*>(&sw1[(dq * 4 + dd) * NHID]);
#pragma unroll
            for (int k = 0; k < 16; k++) fma2(acc2[k], xx, w1p[k]);
        }
    }

    // gelu (exact erf) + repack pairs.
    unsigned long long hp[16];
#pragma unroll
    for (int k = 0; k < 16; k++) {
        float2 v = unpack2(acc2[k]);
        hp[k] = pack2(gelu_exact(v.x), gelu_exact(v.y));
    }

    // 11 masked W entries: w[o] = h . fW2[:, (n+off)%1024] + fb2[(n+off)%1024]
    const int OFF[NOFF] = {0, 1, 2, 4, 8, 16, 32, 64, 128, 256, 512};
#pragma unroll
    for (int o = 0; o < NOFF; o++) {
        int c = t + OFF[o];
        int m = (n0 + c) & (NVEC - 1);
        unsigned long long a2 = pack2(0.f, 0.f);
        const unsigned long long* w2p =
            reinterpret_cast<const unsigned long long*>(&sw2t[c * SW2_STRIDE]);
#pragma unroll
        for (int k = 0; k < 16; k++) fma2(a2, hp[k], w2p[k]);
        float2 s = unpack2(a2);
        g_w[(size_t)((i * NB + b) * NOFF + o) * NVEC + n] =
            s.x + s.y + __ldg(&fb2[i * NVEC + m]);
    }
}

// ---------------------------------------------------------------------------
// Kernel 2: the full 10-layer sparse recursion, V slice resident in smem.
// grid (8 d-groups of 8 dims, 16 b), 1024 threads; thread t owns row n = t.
// smem layout Vs[d][1024] (transposed) -> every LDS is conflict-free.
// ---------------------------------------------------------------------------
__global__ void __launch_bounds__(1024) recurse_kernel(const float* __restrict__ data)
{
    __shared__ float Vs[8 * NVEC];
    const int t  = threadIdx.x;
    const int d0 = blockIdx.x * 8;
    const int b  = blockIdx.y;

    const float4* p =
        reinterpret_cast<const float4*>(data + ((size_t)(b * NVEC) + t) * NDIM + d0);
    float4 A  = __ldg(p);
    float4 Bv = __ldg(p + 1);
    Vs[0 * NVEC + t] = A.x;  Vs[1 * NVEC + t] = A.y;
    Vs[2 * NVEC + t] = A.z;  Vs[3 * NVEC + t] = A.w;
    Vs[4 * NVEC + t] = Bv.x; Vs[5 * NVEC + t] = Bv.y;
    Vs[6 * NVEC + t] = Bv.z; Vs[7 * NVEC + t] = Bv.w;
    __syncthreads();

    const int OFF[NOFF] = {0, 1, 2, 4, 8, 16, 32, 64, 128, 256, 512};
    float acc[8];

    for (int i = NW - 1; i >= 0; i--) {          // reference iterates layers in reverse
        const float* w = g_w + (size_t)((i * NB + b) * NOFF) * NVEC;
        float wv[NOFF];
#pragma unroll
        for (int o = 0; o < NOFF; o++) wv[o] = __ldg(&w[o * NVEC + t]);

#pragma unroll
        for (int d = 0; d < 8; d++) acc[d] = Vs[d * NVEC + t];   // residual
#pragma unroll
        for (int o = 0; o < NOFF; o++) {
            int m = (t + OFF[o]) & (NVEC - 1);
#pragma unroll
            for (int d = 0; d < 8; d++) acc[d] += wv[o] * Vs[d * NVEC + m];
        }
        __syncthreads();          // all reads of old V done
#pragma unroll
        for (int d = 0; d < 8; d++) Vs[d * NVEC + t] = acc[d];
        __syncthreads();          // new V visible
    }

    float* outp = g_V + ((size_t)(b * NVEC) + t) * NDIM + d0;
    *reinterpret_cast<float4*>(outp)     = make_float4(acc[0], acc[1], acc[2], acc[3]);
    *reinterpret_cast<float4*>(outp + 4) = make_float4(acc[4], acc[5], acc[6], acc[7]);
}

// ---------------------------------------------------------------------------
// Kernel 3: partial output GEMM  (16 x 65536) @ (65536 x 10), split 8 ways.
// grid (8 chunks, 16 b), 1024 threads; thread owns 8 contiguous flat indices.
// final_W read fully vectorized as LDG.128. Deterministic (no atomics).
// ---------------------------------------------------------------------------
__global__ void __launch_bounds__(1024) partial_kernel(const float* __restrict__ finW)
{
    const int t  = threadIdx.x;
    const int ch = blockIdx.x;   // 0..7
    const int b  = blockIdx.y;
    const int f0 = ch * 8192 + t * 8;

    const float* Vb = g_V + ((size_t)b << 16);
    float4 v0 = *reinterpret_cast<const float4*>(Vb + f0);
    float4 v1 = *reinterpret_cast<const float4*>(Vb + f0 + 4);
    float vv[8] = {v0.x, v0.y, v0.z, v0.w, v1.x, v1.y, v1.z, v1.w};

    float acc[10];
#pragma unroll
    for (int c = 0; c < 10; c++) acc[c] = 0.f;

    const float4* Wp = reinterpret_cast<const float4*>(finW + (size_t)f0 * 10);
#pragma unroll
    for (int u = 0; u < 4; u++) {                 // 2 f per unit -> 20 floats = 5 float4
        float4 w4[5];
#pragma unroll
        for (int j = 0; j < 5; j++) w4[j] = __ldg(Wp + u * 5 + j);
        const float* wf = reinterpret_cast<const float*>(w4);
        float va = vv[2 * u], vb = vv[2 * u + 1];
#pragma unroll
        for (int c = 0; c < 10; c++) acc[c] += va * wf[c];
#pragma unroll
        for (int c = 0; c < 10; c++) acc[c] += vb * wf[10 + c];
    }

    // warp reduce, then block reduce via smem (deterministic).
#pragma unroll
    for (int c = 0; c < 10; c++) {
#pragma unroll
        for (int s = 16; s > 0; s >>= 1)
            acc[c] += __shfl_xor_sync(0xffffffffu, acc[c], s);
    }
    __shared__ float red[32 * 10];
    int lane = t & 31, wp = t >> 5;
    if (lane == 0) {
#pragma unroll
        for (int c = 0; c < 10; c++) red[wp * 10 + c] = acc[c];
    }
    __syncthreads();
    if (t < 10) {
        float s = 0.f;
        for (int w_ = 0; w_ < 32; w_++) s += red[w_ * 10 + t];
        g_part[(b * 8 + ch) * 10 + t] = s;
    }
}

__global__ void reduce_kernel(const float* __restrict__ finb, float* __restrict__ out)
{
    int t = threadIdx.x;
    if (t < NB * 10) {
        int b = t / 10, c = t - b * 10;
        float s = finb[c];
#pragma unroll
        for (int ch = 0; ch < 8; ch++) s += g_part[(b * 8 + ch) * 10 + c];
        out[t] = s;
    }
}

// ---------------------------------------------------------------------------
extern "C" void kernel_launch(void* const* d_in, const int* in_sizes, int n_in,
                              void* d_out, int out_size)
{
    const float* data = (const float*)d_in[0];
    const float* fW1  = (const float*)d_in[1];
    const float* fb1  = (const float*)d_in[2];
    const float* fW2  = (const float*)d_in[3];
    const float* fb2  = (const float*)d_in[4];
    const float* finW = (const float*)d_in[5];
    const float* finb = (const float*)d_in[6];
    float* out = (float*)d_out;

    cudaFuncSetAttribute(precompute_kernel,
                         cudaFuncAttributeMaxDynamicSharedMemorySize, PRE_SMEM);

    precompute_kernel<<<dim3(4, 16, 10), 256, PRE_SMEM>>>(data, fW1, fb1, fW2, fb2);
    recurse_kernel<<<dim3(8, 16), 1024>>>(data);
    partial_kernel<<<dim3(8, 16), 1024>>>(finW);
    reduce_kernel<<<1, 192>>>(finb, out);
}